// round 5
// baseline (speedup 1.0000x reference)
#include <cuda_runtime.h>
#include <cuda_bf16.h>

// Two horizontally-adjacent patches per thread, packed f32x2 arithmetic.
// R5: qubit-0 RX folded analytically into the Walsh observables
//     (PZ sums/diffs of qubit-0 pairs in terms of pre-butterfly |a|^2 and
//      cross term Im(a_s* a_t)), plus gentle reg target of 72 (28 warps/SM).
//
// Algebra (validated R1-R4, rel_err ~9e-7):
//  * encoding diagonal after H^4: a(s) = (1/4) e^{i Psi(s)}, Psi via CSE tree
//  * RX butterflies for qubits 1,2,3 only
//  * qubit-0 RX + CNOT-ring Walsh masks {7,12,14,15} evaluated as:
//      SUM_p = N_s + N_t                          (mask 7 path)
//      DIF_p = cos(w0)(N_s - N_t) + 2 sin(w0) C   (masks 12,14,15 path)
//      C = Im(a_s* a_t)
//  * 1/16 scale folded into final outputs

typedef unsigned long long u64;

__device__ __forceinline__ u64 pk2(float lo, float hi) {
    u64 r; asm("mov.b64 %0,{%1,%2};" : "=l"(r) : "f"(lo), "f"(hi)); return r;
}
__device__ __forceinline__ void unpk(u64 v, float& lo, float& hi) {
    asm("mov.b64 {%0,%1},%2;" : "=f"(lo), "=f"(hi) : "l"(v));
}
__device__ __forceinline__ u64 add2(u64 a, u64 b) {
    u64 d; asm("add.rn.f32x2 %0,%1,%2;" : "=l"(d) : "l"(a), "l"(b)); return d;
}
__device__ __forceinline__ u64 sub2(u64 a, u64 b) {
    u64 d; asm("sub.rn.f32x2 %0,%1,%2;" : "=l"(d) : "l"(a), "l"(b)); return d;
}
__device__ __forceinline__ u64 mul2(u64 a, u64 b) {
    u64 d; asm("mul.rn.f32x2 %0,%1,%2;" : "=l"(d) : "l"(a), "l"(b)); return d;
}
__device__ __forceinline__ u64 fma2(u64 a, u64 b, u64 c) {
    u64 d; asm("fma.rn.f32x2 %0,%1,%2,%3;" : "=l"(d) : "l"(a), "l"(b), "l"(c)); return d;
}

__global__ void __launch_bounds__(128, 7)
qconv_kernel(const float* __restrict__ img,
             const float* __restrict__ wts,
             float* __restrict__ out,
             int npair)
{
    int tid = blockIdx.x * blockDim.x + threadIdx.x;
    if (tid >= npair) return;

    int b    = tid / 98;            // image
    int rem2 = tid - b * 98;        // j*7 + k2
    int j    = rem2 / 7;
    int k2   = rem2 - j * 7;

    const float4* rp = reinterpret_cast<const float4*>(
        img + (size_t)b * 784 + (size_t)(2 * j) * 28 + (size_t)(4 * k2));
    float4 q0 = rp[0];   // row 2j  : A.x0 A.x1 B.x0 B.x1
    float4 q1 = rp[7];   // row 2j+1: A.x2 A.x3 B.x2 B.x3

    u64 x0 = pk2(q0.x, q0.z);
    u64 x1 = pk2(q0.y, q0.w);
    u64 x2 = pk2(q1.x, q1.z);
    u64 x3 = pk2(q1.y, q1.w);

    const u64 HR2 = pk2(0.3925f, 0.3925f);   // 0.785/2
    u64 h0 = mul2(x0, HR2), h1 = mul2(x1, HR2);
    u64 h2 = mul2(x2, HR2), h3 = mul2(x3, HR2);
    u64 p01 = mul2(h0, x1), p02 = mul2(h0, x2), p03 = mul2(h0, x3);
    u64 p12 = mul2(h1, x2), p13 = mul2(h1, x3), p23 = mul2(h2, x3);

    // single-qubit phase bases
    u64 a01 = add2(h0, h1), b01 = sub2(h0, h1);
    u64 a23 = add2(h2, h3), b23 = sub2(h2, h3);
    u64 SA = add2(a01, a23), SB = sub2(a01, a23);
    u64 SC = add2(b01, a23), SD = sub2(b01, a23);
    u64 SE = add2(a01, b23), SF = sub2(a01, b23);
    u64 SG = add2(b01, b23), SH = sub2(b01, b23);

    // pair phase bases
    u64 m = add2(p12, p13), n = sub2(p12, p13);
    u64 t_pp = sub2(p01, m), t_mm = add2(p01, m);
    u64 t_pm = sub2(p01, n), t_mp = add2(p01, n);
    u64 u = add2(p02, p03), v = sub2(p02, p03);
    u64 q_pp = sub2(u, p23), q_mm = add2(u, p23);
    u64 q_pm = add2(v, p23), q_mp = sub2(v, p23);

    u64 P111  = add2(t_pp, q_pp);
    u64 P110  = add2(t_pm, q_pm);
    u64 P101  = sub2(t_mp, q_mp);
    u64 P100  = sub2(t_mm, q_mm);
    u64 P011  = sub2(q_pp, t_pp);
    u64 P010  = sub2(q_pm, t_pm);
    u64 Pn001 = add2(t_mp, q_mp);
    u64 Pn000 = add2(t_mm, q_mm);

    u64 psi[16];
    psi[0]  = sub2(0ULL, add2(SA, Pn000));   // 0ULL == packed (0.0f,0.0f)
    psi[1]  = sub2(0ULL, add2(SE, Pn001));
    psi[2]  = sub2(P010, SF);
    psi[3]  = sub2(P011, SB);
    psi[4]  = sub2(P100, SC);
    psi[5]  = sub2(P101, SG);
    psi[6]  = sub2(P110, SH);
    psi[7]  = sub2(P111, SD);
    psi[8]  = add2(SD, P111);
    psi[9]  = add2(SH, P110);
    psi[10] = add2(SG, P101);
    psi[11] = add2(SC, P100);
    psi[12] = add2(SB, P011);
    psi[13] = add2(SF, P010);
    psi[14] = sub2(SE, Pn001);
    psi[15] = sub2(SA, Pn000);

    // amplitudes (unscaled): per-lane sincos
    u64 AR[16], AI[16];
#pragma unroll
    for (int s = 0; s < 16; ++s) {
        float pa, pb, sa, ca, sb, cb;
        unpk(psi[s], pa, pb);
        __sincosf(pa, &sa, &ca);
        __sincosf(pb, &sb, &cb);
        AR[s] = pk2(ca, cb);
        AI[s] = pk2(sa, sb);
    }

    // RX butterflies for qubits 1,2,3 only (bits 4,2,1)
#pragma unroll
    for (int q = 1; q < 4; ++q) {
        float sw, cw;
        __sincosf(__ldg(wts + q) * 0.5f, &sw, &cw);
        u64 cw2 = pk2(cw, cw), sw2 = pk2(sw, sw);
        int bit = 1 << (3 - q);
#pragma unroll
        for (int s = 0; s < 16; ++s) {
            if (s & bit) continue;
            int t = s | bit;
            u64 a0r = AR[s], a0i = AI[s];
            u64 a1r = AR[t], a1i = AI[t];
            AR[s] = fma2(cw2, a0r, mul2(sw2, a1i));
            AI[s] = sub2(mul2(cw2, a0i), mul2(sw2, a1r));
            AR[t] = fma2(cw2, a1r, mul2(sw2, a0i));
            AI[t] = sub2(mul2(cw2, a1i), mul2(sw2, a0r));
        }
    }

    // qubit-0 RX folded analytically: per pair (s, s+8)
    //   SUM_p = N_s + N_t
    //   DIF_p = cos(w0)*(N_s - N_t) + 2 sin(w0)*Im(a_s* a_t)
    float s0, c0;
    __sincosf(__ldg(wts + 0), &s0, &c0);     // full angle w0
    u64 c0p  = pk2(c0, c0);
    u64 s0p2 = pk2(2.0f * s0, 2.0f * s0);

    u64 SUMp[8], DIFp[8];
#pragma unroll
    for (int s = 0; s < 8; ++s) {
        int t = s + 8;
        u64 Ns = fma2(AI[s], AI[s], mul2(AR[s], AR[s]));
        u64 Nt = fma2(AI[t], AI[t], mul2(AR[t], AR[t]));
        u64 Cx = sub2(mul2(AR[s], AI[t]), mul2(AI[s], AR[t]));
        SUMp[s] = add2(Ns, Nt);
        u64 Nd  = sub2(Ns, Nt);
        DIFp[s] = fma2(c0p, Nd, mul2(s0p2, Cx));
    }

    // Walsh trees over the 8 pairs (pair index bits = b1 b2 b3):
    //  E7  = sum (-1)^{b1+b2+b3} SUM_p
    //  E15 = sum (-1)^{b1+b2+b3} DIF_p
    //  E12 = sum (-1)^{b1}       DIF_p
    //  E14 = sum (-1)^{b1+b2}    DIF_p
    u64 uarr[4], varr[4];
#pragma unroll
    for (int k = 0; k < 4; ++k) {
        uarr[k] = add2(DIFp[2 * k], DIFp[2 * k + 1]);
        varr[k] = sub2(DIFp[2 * k], DIFp[2 * k + 1]);
    }
    u64 E15 = sub2(sub2(varr[0], varr[1]), sub2(varr[2], varr[3]));
    u64 E12 = sub2(add2(uarr[0], uarr[1]), add2(uarr[2], uarr[3]));
    u64 E14 = sub2(sub2(uarr[0], uarr[1]), sub2(uarr[2], uarr[3]));

    u64 warr[4];
#pragma unroll
    for (int k = 0; k < 4; ++k)
        warr[k] = sub2(SUMp[2 * k], SUMp[2 * k + 1]);
    u64 E7 = sub2(sub2(warr[0], warr[1]), sub2(warr[2], warr[3]));

    const u64 SC16 = pk2(0.0625f, 0.0625f);
    u64 ez0 = mul2(E7,  SC16);   // mask 7  -> Z0
    u64 ez1 = mul2(E12, SC16);   // mask 12 -> Z1
    u64 ez2 = mul2(E14, SC16);   // mask 14 -> Z2
    u64 ez3 = mul2(E15, SC16);   // mask 15 -> Z3

    // output (B,4,14,14), channels [Z3,Z2,Z1,Z0]; adjacent pair -> STG.64
    float* o = out + (size_t)b * 784 + (size_t)j * 14 + (size_t)(2 * k2);
    *reinterpret_cast<u64*>(o)       = ez3;
    *reinterpret_cast<u64*>(o + 196) = ez2;
    *reinterpret_cast<u64*>(o + 392) = ez1;
    *reinterpret_cast<u64*>(o + 588) = ez0;
}

extern "C" void kernel_launch(void* const* d_in, const int* in_sizes, int n_in,
                              void* d_out, int out_size) {
    const float* img = (const float*)d_in[0];
    const float* wts = (const float*)d_in[1];
    float* out = (float*)d_out;

    int B = in_sizes[0] / 784;
    int npair = B * 98;             // 14 * 7 patch-pairs per image

    int threads = 128;
    int blocks = (npair + threads - 1) / threads;
    qconv_kernel<<<blocks, threads>>>(img, wts, out, npair);
}

// round 6
// speedup vs baseline: 1.1311x; 1.1311x over previous
#include <cuda_runtime.h>
#include <cuda_bf16.h>

// Two horizontally-adjacent patches per thread, packed f32x2 arithmetic.
// R6 = R5 algebra (qubit-0 RX folded into the Walsh observables) at R3's
// natural register allocation (NO launch-bounds occupancy cap -> no spills),
// with 64-thread blocks for finer wave-tail granularity.
//
// Algebra (validated R1-R5, rel_err ~9e-7):
//  * encoding diagonal after H^4: a(s) = (1/4) e^{i Psi(s)}, Psi via CSE tree
//  * RX butterflies for qubits 1,2,3 only
//  * qubit-0 RX + CNOT-ring Walsh masks {7,12,14,15}:
//      SUM_p = N_s + N_t                            (mask 7)
//      DIF_p = cos(w0)(N_s - N_t) + 2 sin(w0) Im(a_s* a_t)   (masks 12,14,15)
//  * 1/16 scale folded into outputs

typedef unsigned long long u64;

__device__ __forceinline__ u64 pk2(float lo, float hi) {
    u64 r; asm("mov.b64 %0,{%1,%2};" : "=l"(r) : "f"(lo), "f"(hi)); return r;
}
__device__ __forceinline__ void unpk(u64 v, float& lo, float& hi) {
    asm("mov.b64 {%0,%1},%2;" : "=f"(lo), "=f"(hi) : "l"(v));
}
__device__ __forceinline__ u64 add2(u64 a, u64 b) {
    u64 d; asm("add.rn.f32x2 %0,%1,%2;" : "=l"(d) : "l"(a), "l"(b)); return d;
}
__device__ __forceinline__ u64 sub2(u64 a, u64 b) {
    u64 d; asm("sub.rn.f32x2 %0,%1,%2;" : "=l"(d) : "l"(a), "l"(b)); return d;
}
__device__ __forceinline__ u64 mul2(u64 a, u64 b) {
    u64 d; asm("mul.rn.f32x2 %0,%1,%2;" : "=l"(d) : "l"(a), "l"(b)); return d;
}
__device__ __forceinline__ u64 fma2(u64 a, u64 b, u64 c) {
    u64 d; asm("fma.rn.f32x2 %0,%1,%2,%3;" : "=l"(d) : "l"(a), "l"(b), "l"(c)); return d;
}

__global__ void __launch_bounds__(64)
qconv_kernel(const float* __restrict__ img,
             const float* __restrict__ wts,
             float* __restrict__ out,
             int npair)
{
    int tid = blockIdx.x * blockDim.x + threadIdx.x;
    if (tid >= npair) return;

    int b    = tid / 98;            // image
    int rem2 = tid - b * 98;        // j*7 + k2
    int j    = rem2 / 7;
    int k2   = rem2 - j * 7;

    const float4* rp = reinterpret_cast<const float4*>(
        img + (size_t)b * 784 + (size_t)(2 * j) * 28 + (size_t)(4 * k2));
    float4 q0 = rp[0];   // row 2j  : A.x0 A.x1 B.x0 B.x1
    float4 q1 = rp[7];   // row 2j+1: A.x2 A.x3 B.x2 B.x3

    u64 x0 = pk2(q0.x, q0.z);
    u64 x1 = pk2(q0.y, q0.w);
    u64 x2 = pk2(q1.x, q1.z);
    u64 x3 = pk2(q1.y, q1.w);

    const u64 HR2 = pk2(0.3925f, 0.3925f);   // 0.785/2
    u64 h0 = mul2(x0, HR2), h1 = mul2(x1, HR2);
    u64 h2 = mul2(x2, HR2), h3 = mul2(x3, HR2);
    u64 p01 = mul2(h0, x1), p02 = mul2(h0, x2), p03 = mul2(h0, x3);
    u64 p12 = mul2(h1, x2), p13 = mul2(h1, x3), p23 = mul2(h2, x3);

    // single-qubit phase bases
    u64 a01 = add2(h0, h1), b01 = sub2(h0, h1);
    u64 a23 = add2(h2, h3), b23 = sub2(h2, h3);
    u64 SA = add2(a01, a23), SB = sub2(a01, a23);
    u64 SC = add2(b01, a23), SD = sub2(b01, a23);
    u64 SE = add2(a01, b23), SF = sub2(a01, b23);
    u64 SG = add2(b01, b23), SH = sub2(b01, b23);

    // pair phase bases
    u64 m = add2(p12, p13), n = sub2(p12, p13);
    u64 t_pp = sub2(p01, m), t_mm = add2(p01, m);
    u64 t_pm = sub2(p01, n), t_mp = add2(p01, n);
    u64 u = add2(p02, p03), v = sub2(p02, p03);
    u64 q_pp = sub2(u, p23), q_mm = add2(u, p23);
    u64 q_pm = add2(v, p23), q_mp = sub2(v, p23);

    u64 P111  = add2(t_pp, q_pp);
    u64 P110  = add2(t_pm, q_pm);
    u64 P101  = sub2(t_mp, q_mp);
    u64 P100  = sub2(t_mm, q_mm);
    u64 P011  = sub2(q_pp, t_pp);
    u64 P010  = sub2(q_pm, t_pm);
    u64 Pn001 = add2(t_mp, q_mp);
    u64 Pn000 = add2(t_mm, q_mm);

    u64 psi[16];
    psi[0]  = sub2(0ULL, add2(SA, Pn000));   // 0ULL == packed (0.0f,0.0f)
    psi[1]  = sub2(0ULL, add2(SE, Pn001));
    psi[2]  = sub2(P010, SF);
    psi[3]  = sub2(P011, SB);
    psi[4]  = sub2(P100, SC);
    psi[5]  = sub2(P101, SG);
    psi[6]  = sub2(P110, SH);
    psi[7]  = sub2(P111, SD);
    psi[8]  = add2(SD, P111);
    psi[9]  = add2(SH, P110);
    psi[10] = add2(SG, P101);
    psi[11] = add2(SC, P100);
    psi[12] = add2(SB, P011);
    psi[13] = add2(SF, P010);
    psi[14] = sub2(SE, Pn001);
    psi[15] = sub2(SA, Pn000);

    // amplitudes (unscaled): per-lane sincos
    u64 AR[16], AI[16];
#pragma unroll
    for (int s = 0; s < 16; ++s) {
        float pa, pb, sa, ca, sb, cb;
        unpk(psi[s], pa, pb);
        __sincosf(pa, &sa, &ca);
        __sincosf(pb, &sb, &cb);
        AR[s] = pk2(ca, cb);
        AI[s] = pk2(sa, sb);
    }

    // RX butterflies for qubits 1,2,3 (bits 4,2,1)
#pragma unroll
    for (int q = 1; q < 4; ++q) {
        float sw, cw;
        __sincosf(__ldg(wts + q) * 0.5f, &sw, &cw);
        u64 cw2 = pk2(cw, cw), sw2 = pk2(sw, sw);
        int bit = 1 << (3 - q);
#pragma unroll
        for (int s = 0; s < 16; ++s) {
            if (s & bit) continue;
            int t = s | bit;
            u64 a0r = AR[s], a0i = AI[s];
            u64 a1r = AR[t], a1i = AI[t];
            AR[s] = fma2(cw2, a0r, mul2(sw2, a1i));
            AI[s] = sub2(mul2(cw2, a0i), mul2(sw2, a1r));
            AR[t] = fma2(cw2, a1r, mul2(sw2, a0i));
            AI[t] = sub2(mul2(cw2, a1i), mul2(sw2, a0r));
        }
    }

    // qubit-0 RX folded analytically over pairs (s, s+8)
    float s0, c0;
    __sincosf(__ldg(wts + 0), &s0, &c0);     // full angle w0
    u64 c0p  = pk2(c0, c0);
    u64 s0p2 = pk2(2.0f * s0, 2.0f * s0);

    u64 SUMp[8], DIFp[8];
#pragma unroll
    for (int s = 0; s < 8; ++s) {
        int t = s + 8;
        u64 Ns = fma2(AI[s], AI[s], mul2(AR[s], AR[s]));
        u64 Nt = fma2(AI[t], AI[t], mul2(AR[t], AR[t]));
        u64 Cx = sub2(mul2(AR[s], AI[t]), mul2(AI[s], AR[t]));
        SUMp[s] = add2(Ns, Nt);
        u64 Nd  = sub2(Ns, Nt);
        DIFp[s] = fma2(c0p, Nd, mul2(s0p2, Cx));
    }

    // Walsh trees over the 8 pairs (pair index bits = b1 b2 b3)
    u64 uarr[4], varr[4];
#pragma unroll
    for (int k = 0; k < 4; ++k) {
        uarr[k] = add2(DIFp[2 * k], DIFp[2 * k + 1]);
        varr[k] = sub2(DIFp[2 * k], DIFp[2 * k + 1]);
    }
    u64 E15 = sub2(sub2(varr[0], varr[1]), sub2(varr[2], varr[3]));
    u64 E12 = sub2(add2(uarr[0], uarr[1]), add2(uarr[2], uarr[3]));
    u64 E14 = sub2(sub2(uarr[0], uarr[1]), sub2(uarr[2], uarr[3]));

    u64 warr[4];
#pragma unroll
    for (int k = 0; k < 4; ++k)
        warr[k] = sub2(SUMp[2 * k], SUMp[2 * k + 1]);
    u64 E7 = sub2(sub2(warr[0], warr[1]), sub2(warr[2], warr[3]));

    const u64 SC16 = pk2(0.0625f, 0.0625f);
    u64 ez0 = mul2(E7,  SC16);   // mask 7  -> Z0
    u64 ez1 = mul2(E12, SC16);   // mask 12 -> Z1
    u64 ez2 = mul2(E14, SC16);   // mask 14 -> Z2
    u64 ez3 = mul2(E15, SC16);   // mask 15 -> Z3

    // output (B,4,14,14), channels [Z3,Z2,Z1,Z0]; adjacent pair -> STG.64
    float* o = out + (size_t)b * 784 + (size_t)j * 14 + (size_t)(2 * k2);
    *reinterpret_cast<u64*>(o)       = ez3;
    *reinterpret_cast<u64*>(o + 196) = ez2;
    *reinterpret_cast<u64*>(o + 392) = ez1;
    *reinterpret_cast<u64*>(o + 588) = ez0;
}

extern "C" void kernel_launch(void* const* d_in, const int* in_sizes, int n_in,
                              void* d_out, int out_size) {
    const float* img = (const float*)d_in[0];
    const float* wts = (const float*)d_in[1];
    float* out = (float*)d_out;

    int B = in_sizes[0] / 784;
    int npair = B * 98;             // 14 * 7 patch-pairs per image

    int threads = 64;
    int blocks = (npair + threads - 1) / threads;
    qconv_kernel<<<blocks, threads>>>(img, wts, out, npair);
}

// round 7
// speedup vs baseline: 1.1335x; 1.0021x over previous
#include <cuda_runtime.h>
#include <cuda_bf16.h>

// One patch per thread; 16 amplitudes packed as 8 f32x2 complex values with
// lane0 = amplitude m, lane1 = amplitude 15-m  (m = 0..7).
// This halves the register live set vs R6 (32 amp regs instead of 64),
// buying occupancy, while the packed butterflies keep working verbatim:
//   psi[m] = P_m - S_m, psi[15-m] = P_m + S_m
//   butterfly pairs (m, m^b) <-> (15-m, (15-m)^b) satisfy the same formulas.
//
// Algebra (validated R1-R6, rel_err ~9e-7):
//  * encoding diagonal after H^4, Psi via CSE tree
//  * RX butterflies for qubits 1,2,3 (bits 4,2,1) on the packed pairs
//  * qubit-0 RX + CNOT-ring Walsh masks {7,12,14,15} folded analytically:
//      SUM_s = N_s + N_{s+8}
//      DIF_s = cos(w0)(N_s - N_{s+8}) + 2 sin(w0) Im(a_s* a_{s+8})
//  * 1/16 scale folded into outputs

typedef unsigned long long u64;

__device__ __forceinline__ u64 pk2(float lo, float hi) {
    u64 r; asm("mov.b64 %0,{%1,%2};" : "=l"(r) : "f"(lo), "f"(hi)); return r;
}
__device__ __forceinline__ void unpk(u64 v, float& lo, float& hi) {
    asm("mov.b64 {%0,%1},%2;" : "=f"(lo), "=f"(hi) : "l"(v));
}
__device__ __forceinline__ u64 mul2(u64 a, u64 b) {
    u64 d; asm("mul.rn.f32x2 %0,%1,%2;" : "=l"(d) : "l"(a), "l"(b)); return d;
}
__device__ __forceinline__ u64 fma2(u64 a, u64 b, u64 c) {
    u64 d; asm("fma.rn.f32x2 %0,%1,%2,%3;" : "=l"(d) : "l"(a), "l"(b), "l"(c)); return d;
}
__device__ __forceinline__ u64 sub2(u64 a, u64 b) {
    u64 d; asm("sub.rn.f32x2 %0,%1,%2;" : "=l"(d) : "l"(a), "l"(b)); return d;
}

__global__ void __launch_bounds__(64)
qconv_kernel(const float* __restrict__ img,
             const float* __restrict__ wts,
             float* __restrict__ out,
             int npatch)
{
    int tid = blockIdx.x * blockDim.x + threadIdx.x;
    if (tid >= npatch) return;

    int b   = tid / 196;
    int rem = tid - b * 196;        // j*14 + k
    int j   = rem / 14;
    int k   = rem - j * 14;

    const float* base = img + (size_t)b * 784 + (size_t)(2 * j) * 28 + (size_t)(2 * k);
    float2 r0 = *reinterpret_cast<const float2*>(base);       // x0 x1
    float2 r1 = *reinterpret_cast<const float2*>(base + 28);  // x2 x3
    float x0 = r0.x, x1 = r0.y, x2 = r1.x, x3 = r1.y;

    const float HR = 0.3925f;       // 0.785/2
    float h0 = x0 * HR, h1 = x1 * HR, h2 = x2 * HR, h3 = x3 * HR;
    float p01 = h0 * x1, p02 = h0 * x2, p03 = h0 * x3;
    float p12 = h1 * x2, p13 = h1 * x3, p23 = h2 * x3;

    // single-qubit bases S
    float a01 = h0 + h1, b01 = h0 - h1;
    float a23 = h2 + h3, b23 = h2 - h3;
    float SA = a01 + a23, SB = a01 - a23;
    float SC = b01 + a23, SD = b01 - a23;
    float SE = a01 + b23, SF = a01 - b23;
    float SG = b01 + b23, SH = b01 - b23;

    // pair bases P
    float m_ = p12 + p13, n_ = p12 - p13;
    float t_pp = p01 - m_, t_mm = p01 + m_;
    float t_pm = p01 - n_, t_mp = p01 + n_;
    float u_ = p02 + p03, v_ = p02 - p03;
    float q_pp = u_ - p23, q_mm = u_ + p23;
    float q_pm = v_ + p23, q_mp = v_ - p23;

    // P_m per pair m (lane0 = psi[m] = P - S, lane1 = psi[15-m] = P + S)
    float P0 = -(t_mm + q_mm);  // m=0: S=SA
    float P1 = -(t_mp + q_mp);  // m=1: S=SE
    float P2 = q_pm - t_pm;     // m=2: S=SF
    float P3 = q_pp - t_pp;     // m=3: S=SB
    float P4 = t_mm - q_mm;     // m=4: S=SC
    float P5 = t_mp - q_mp;     // m=5: S=SG
    float P6 = t_pm + q_pm;     // m=6: S=SH
    float P7 = t_pp + q_pp;     // m=7: S=SD

    float Sv[8] = { SA, SE, SF, SB, SC, SG, SH, SD };
    float Pv[8] = { P0, P1, P2, P3, P4, P5, P6, P7 };

    // packed amplitudes: AR[m] = (cos(P-S), cos(P+S)), AI[m] = (sin(P-S), sin(P+S))
    u64 AR[8], AI[8];
#pragma unroll
    for (int m = 0; m < 8; ++m) {
        float lo = Pv[m] - Sv[m];
        float hi = Pv[m] + Sv[m];
        float sl, cl, sh, ch;
        __sincosf(lo, &sl, &cl);
        __sincosf(hi, &sh, &ch);
        AR[m] = pk2(cl, ch);
        AI[m] = pk2(sl, sh);
    }

    // RX butterflies for qubits 1,2,3 (bits 4,2,1) — valid in both lanes by
    // the complement symmetry (lane1 index = 15 - lane0 index).
#pragma unroll
    for (int q = 1; q < 4; ++q) {
        float sw, cw;
        __sincosf(__ldg(wts + q) * 0.5f, &sw, &cw);
        u64 cw2 = pk2(cw, cw), sw2 = pk2(sw, sw);
        int bit = 1 << (3 - q);
#pragma unroll
        for (int m = 0; m < 8; ++m) {
            if (m & bit) continue;
            int t = m | bit;
            u64 a0r = AR[m], a0i = AI[m];
            u64 a1r = AR[t], a1i = AI[t];
            AR[m] = fma2(cw2, a0r, mul2(sw2, a1i));
            AI[m] = sub2(mul2(cw2, a0i), mul2(sw2, a1r));
            AR[t] = fma2(cw2, a1r, mul2(sw2, a0i));
            AI[t] = sub2(mul2(cw2, a1i), mul2(sw2, a0r));
        }
    }

    // qubit-0 fold: pair (s, s+8) lives at lane0 of reg s and lane1 of reg 7-s.
    float s0, c0;
    __sincosf(__ldg(wts + 0), &s0, &c0);
    float s02 = 2.0f * s0;

    float SUM[8], DIF[8];
#pragma unroll
    for (int s = 0; s < 4; ++s) {
        int r7 = 7 - s;
        float arl, arh, ail, aih;       // reg s
        float brl, brh, bil, bih;       // reg 7-s
        unpk(AR[s],  arl, arh);
        unpk(AI[s],  ail, aih);
        unpk(AR[r7], brl, brh);
        unpk(AI[r7], bil, bih);

        // pair s: a_s = (arl, ail), a_{s+8} = (brh, bih)
        {
            float Ns = arl * arl + ail * ail;
            float Nt = brh * brh + bih * bih;
            float Cx = arl * bih - ail * brh;
            SUM[s] = Ns + Nt;
            DIF[s] = c0 * (Ns - Nt) + s02 * Cx;
        }
        // pair 7-s: a_{7-s} = (brl, bil), a_{15-s} = (arh, aih)
        {
            float Ns = brl * brl + bil * bil;
            float Nt = arh * arh + aih * aih;
            float Cx = brl * aih - bil * arh;
            SUM[r7] = Ns + Nt;
            DIF[r7] = c0 * (Ns - Nt) + s02 * Cx;
        }
    }

    // Walsh trees over s = 4*b1 + 2*b2 + b3
    float d0 = DIF[0] - DIF[1], d1 = DIF[2] - DIF[3];
    float d2 = DIF[4] - DIF[5], d3 = DIF[6] - DIF[7];
    float e0 = DIF[0] + DIF[1], e1 = DIF[2] + DIF[3];
    float e2 = DIF[4] + DIF[5], e3 = DIF[6] + DIF[7];

    float E15 = (d0 - d1) - (d2 - d3);
    float E14 = (e0 - e1) - (e2 - e3);
    float E12 = (e0 + e1) - (e2 + e3);

    float w0_ = SUM[0] - SUM[1], w1_ = SUM[2] - SUM[3];
    float w2_ = SUM[4] - SUM[5], w3_ = SUM[6] - SUM[7];
    float E7 = (w0_ - w1_) - (w2_ - w3_);

    const float SC16 = 0.0625f;
    // output (B,4,14,14), channels [Z3,Z2,Z1,Z0]
    float* o = out + (size_t)b * 784 + rem;
    o[0]   = E15 * SC16;   // Z3 (mask 15)
    o[196] = E14 * SC16;   // Z2 (mask 14)
    o[392] = E12 * SC16;   // Z1 (mask 12)
    o[588] = E7  * SC16;   // Z0 (mask 7)
}

extern "C" void kernel_launch(void* const* d_in, const int* in_sizes, int n_in,
                              void* d_out, int out_size) {
    const float* img = (const float*)d_in[0];
    const float* wts = (const float*)d_in[1];
    float* out = (float*)d_out;

    int B = in_sizes[0] / 784;
    int npatch = B * 196;

    int threads = 64;
    int blocks = (npatch + threads - 1) / threads;
    qconv_kernel<<<blocks, threads>>>(img, wts, out, npatch);
}